// round 1
// baseline (speedup 1.0000x reference)
#include <cuda_runtime.h>
#include <cuda_bf16.h>
#include <math.h>

// Problem constants
#define B_  2
#define S_  2048
#define E_  1024
#define H_  1024
#define NH_ 8
#define HD_ 128
#define L_  2
#define V_  32000
#define CS_ 128
#define NC_ 16
#define TOPK_ 8
#define R_  (B_ * S_)       // 4096 rows
#define FF_ (4 * H_)        // 4096
#define HH_ (H_ / 2)        // 512
#define SCALE_ 0.08838834764831843f  // 1/sqrt(128)

// ---------------- scratch (device globals; no allocations allowed) ----------------
__device__ float g_h  [R_ * H_];      // hidden state
__device__ float g_x  [R_ * H_];      // emb / qe / ln output (reused)
__device__ float g_q  [R_ * H_];
__device__ float g_k  [R_ * H_];
__device__ float g_v  [R_ * H_];
__device__ float g_ao [R_ * H_];
__device__ float g_mid[R_ * FF_];     // 64MB: qe1 / ffn mid
__device__ float g_avg [B_ * NC_ * H_];
__device__ float g_cmid[B_ * NC_ * HH_];
__device__ float g_cenc[B_ * NC_ * H_];
__device__ unsigned g_sel[R_];

// ---------------- helpers ----------------
__device__ __forceinline__ float warpSum(float v) {
    #pragma unroll
    for (int o = 16; o > 0; o >>= 1) v += __shfl_xor_sync(0xffffffffu, v, o);
    return v;
}
__device__ __forceinline__ float warpMax(float v) {
    #pragma unroll
    for (int o = 16; o > 0; o >>= 1) v = fmaxf(v, __shfl_xor_sync(0xffffffffu, v, o));
    return v;
}

// ---------------- embedding ----------------
__global__ void embed_kernel(const int* __restrict__ ids, const float* __restrict__ tok,
                             const float* __restrict__ pos, float* __restrict__ out) {
    int r = blockIdx.x;
    int sp = r % S_;
    int id = ids[r];
    const float* t = tok + (size_t)id * E_;
    const float* p = pos + (size_t)sp * E_;
    float* o = out + (size_t)r * E_;
    for (int e = threadIdx.x; e < E_; e += blockDim.x) o[e] = t[e] + p[e];
}

// ---------------- generic SGEMM: C = act(A@W + bias) [+ res] ----------------
// A:[M,K] row-major, W:[K,N] row-major. Requires K%16==0, N%128==0. M guarded.
// act: 0=none, 1=relu, 2=gelu(exact)
__global__ void __launch_bounds__(256)
gemm_kernel(const float* __restrict__ A, const float* __restrict__ W,
            const float* __restrict__ bias, const float* __restrict__ res,
            float* __restrict__ C, int M, int K, int N, int act) {
    __shared__ float As[16][128];
    __shared__ float Bs[16][128];
    const int tid = threadIdx.x;
    const int tx = tid & 15, ty = tid >> 4;
    const int m0 = blockIdx.y * 128, n0 = blockIdx.x * 128;

    const int ar = tid >> 1;           // 0..127 (A row within tile)
    const int aseg = (tid & 1) * 8;    // 0 or 8 (k segment)
    const int br = tid >> 4;           // 0..15 (B row = k)
    const int bc = (tid & 15) * 4;     // 0..60

    float acc[8][8];
    #pragma unroll
    for (int i = 0; i < 8; i++)
        #pragma unroll
        for (int j = 0; j < 8; j++) acc[i][j] = 0.f;

    for (int k0 = 0; k0 < K; k0 += 16) {
        float4 a0, a1;
        if (m0 + ar < M) {
            const float* ap = A + (size_t)(m0 + ar) * K + k0 + aseg;
            a0 = *(const float4*)ap;
            a1 = *(const float4*)(ap + 4);
        } else {
            a0 = make_float4(0.f, 0.f, 0.f, 0.f);
            a1 = a0;
        }
        As[aseg + 0][ar] = a0.x; As[aseg + 1][ar] = a0.y;
        As[aseg + 2][ar] = a0.z; As[aseg + 3][ar] = a0.w;
        As[aseg + 4][ar] = a1.x; As[aseg + 5][ar] = a1.y;
        As[aseg + 6][ar] = a1.z; As[aseg + 7][ar] = a1.w;

        const float* bp = W + (size_t)(k0 + br) * N + n0;
        *(float4*)&Bs[br][bc]      = *(const float4*)(bp + bc);
        *(float4*)&Bs[br][bc + 64] = *(const float4*)(bp + bc + 64);
        __syncthreads();

        #pragma unroll
        for (int kk = 0; kk < 16; kk++) {
            float a[8], b[8];
            *(float4*)&a[0] = *(float4*)&As[kk][ty * 8];
            *(float4*)&a[4] = *(float4*)&As[kk][ty * 8 + 4];
            *(float4*)&b[0] = *(float4*)&Bs[kk][tx * 8];
            *(float4*)&b[4] = *(float4*)&Bs[kk][tx * 8 + 4];
            #pragma unroll
            for (int i = 0; i < 8; i++)
                #pragma unroll
                for (int j = 0; j < 8; j++) acc[i][j] += a[i] * b[j];
        }
        __syncthreads();
    }

    #pragma unroll
    for (int i = 0; i < 8; i++) {
        int row = m0 + ty * 8 + i;
        if (row >= M) break;
        size_t off = (size_t)row * N + n0 + tx * 8;
        #pragma unroll
        for (int j = 0; j < 8; j++) {
            float v = acc[i][j] + bias[n0 + tx * 8 + j];
            if (act == 1) v = fmaxf(v, 0.f);
            else if (act == 2) v = 0.5f * v * (1.f + erff(v * 0.7071067811865475f));
            if (res) v += res[off + j];
            C[off + j] = v;
        }
    }
}

// ---------------- chunk mean ----------------
__global__ void chunk_avg_kernel(const float* __restrict__ h, const int* __restrict__ ids,
                                 float* __restrict__ avg) {
    int c = blockIdx.x, b = blockIdx.y;
    __shared__ float msk[CS_];
    __shared__ float s_cnt;
    int tid = threadIdx.x;
    if (tid < CS_) msk[tid] = (ids[b * S_ + c * CS_ + tid] != 0) ? 1.f : 0.f;
    __syncthreads();
    if (tid == 0) {
        float cn = 0.f;
        for (int p = 0; p < CS_; p++) cn += msk[p];
        s_cnt = cn;
    }
    __syncthreads();
    float inv = 1.f / (s_cnt + 1e-10f);
    for (int d = tid; d < H_; d += blockDim.x) {
        float s = 0.f;
        for (int p = 0; p < CS_; p++)
            s += h[(size_t)(b * S_ + c * CS_ + p) * H_ + d] * msk[p];
        avg[(size_t)(b * NC_ + c) * H_ + d] = s * inv;
    }
}

// ---------------- cscores + top-k chunk selection ----------------
__global__ void __launch_bounds__(512)
topk_kernel(const float* __restrict__ qe, const float* __restrict__ cenc,
            unsigned* __restrict__ sel) {
    int s = blockIdx.x, b = blockIdx.y;
    int tid = threadIdx.x, warp = tid >> 5, lane = tid & 31;
    __shared__ float sc[NC_];
    const float* q = qe + (size_t)(b * S_ + s) * H_;
    const float* c = cenc + (size_t)(b * NC_ + warp) * H_;
    float d = 0.f;
    for (int e = lane; e < H_; e += 32) d += q[e] * c[e];
    d = warpSum(d);
    if (lane == 0) sc[warp] = d;
    __syncthreads();
    if (tid == 0) {
        unsigned chosen = 0;
        for (int t = 0; t < TOPK_; t++) {
            float best = -INFINITY;
            int bi = 0;
            for (int cc = 0; cc < NC_; cc++)
                if (!((chosen >> cc) & 1u) && sc[cc] > best) { best = sc[cc]; bi = cc; }
            chosen |= 1u << bi;
        }
        sel[b * S_ + s] = chosen;
    }
}

// ---------------- LayerNorm ----------------
__global__ void ln_kernel(const float* __restrict__ x, const float* __restrict__ g,
                          const float* __restrict__ bt, float* __restrict__ y) {
    int r = blockIdx.x;
    int tid = threadIdx.x, warp = tid >> 5, lane = tid & 31;
    const float* xr = x + (size_t)r * H_;
    float s = 0.f, sq = 0.f;
    for (int e = tid; e < H_; e += 256) {
        float v = xr[e];
        s += v; sq += v * v;
    }
    __shared__ float rs[8], rq[8];
    __shared__ float s_mean, s_rstd;
    s = warpSum(s); sq = warpSum(sq);
    if (lane == 0) { rs[warp] = s; rq[warp] = sq; }
    __syncthreads();
    if (tid == 0) {
        float S = 0.f, Q = 0.f;
        for (int w = 0; w < 8; w++) { S += rs[w]; Q += rq[w]; }
        float mean = S / (float)H_;
        float var = Q / (float)H_ - mean * mean;
        s_mean = mean;
        s_rstd = rsqrtf(var + 1e-5f);
    }
    __syncthreads();
    float mean = s_mean, rstd = s_rstd;
    float* yr = y + (size_t)r * H_;
    for (int e = tid; e < H_; e += 256)
        yr[e] = (xr[e] - mean) * rstd * g[e] + bt[e];
}

// ---------------- sparse chunk attention (one block per (b, head, query)) ----------------
__global__ void __launch_bounds__(128)
attn_kernel(const float* __restrict__ q, const float* __restrict__ k,
            const float* __restrict__ v, const unsigned* __restrict__ sel,
            const int* __restrict__ ids, float* __restrict__ out) {
    int s = blockIdx.x, head = blockIdx.y, b = blockIdx.z;
    int tid = threadIdx.x, warp = tid >> 5, lane = tid & 31;
    __shared__ float qv[HD_];
    __shared__ float sc[CS_];
    __shared__ float red[4];
    __shared__ float bcast[2];

    size_t qoff = (size_t)(b * S_ + s) * H_ + head * HD_;
    qv[tid] = q[qoff + tid];
    __syncthreads();
    float4 q4 = *(const float4*)&qv[lane * 4];

    unsigned msk = sel[b * S_ + s];
    float m = -INFINITY, l = 0.f, acc = 0.f;

    for (int c = 0; c < NC_; c++) {
        if (!((msk >> c) & 1u)) continue;
        int j0 = c * CS_;
        // scores: 4 warps x 32 keys each
        for (int kk = 0; kk < 32; kk++) {
            int j = j0 + warp * 32 + kk;
            const float4 kv = *(const float4*)&k[(size_t)(b * S_ + j) * H_ + head * HD_ + lane * 4];
            float d = q4.x * kv.x + q4.y * kv.y + q4.z * kv.z + q4.w * kv.w;
            d = warpSum(d);
            if (lane == 0) sc[warp * 32 + kk] = d;
        }
        __syncthreads();
        float scv = sc[tid] * SCALE_;
        if (ids[b * S_ + j0 + tid] == 0) scv = -INFINITY;
        float wm = warpMax(scv);
        if (lane == 0) red[warp] = wm;
        __syncthreads();
        if (tid == 0) {
            float mm = red[0];
            mm = fmaxf(mm, red[1]); mm = fmaxf(mm, red[2]); mm = fmaxf(mm, red[3]);
            bcast[0] = mm;
        }
        __syncthreads();
        float cmax = bcast[0];
        float newm = fmaxf(m, cmax);
        float p = expf(scv - newm);
        sc[tid] = p;
        float ws = warpSum(p);
        if (lane == 0) red[warp] = ws;
        __syncthreads();
        if (tid == 0) bcast[1] = red[0] + red[1] + red[2] + red[3];
        __syncthreads();
        float csum = bcast[1];
        float f = expf(m - newm);
        l = l * f + csum;
        acc *= f;
        const float* vb = v + (size_t)(b * S_ + j0) * H_ + head * HD_ + tid;
        for (int j = 0; j < CS_; j++) acc += sc[j] * vb[(size_t)j * H_];
        m = newm;
        __syncthreads();
    }
    out[qoff + tid] = acc / l;
}

// ---------------- host-side orchestration ----------------
static inline void launch_gemm(const float* A, const float* W, const float* bias,
                               const float* res, float* C, int M, int K, int N, int act) {
    dim3 grid(N / 128, (M + 127) / 128);
    gemm_kernel<<<grid, 256>>>(A, W, bias, res, C, M, K, N, act);
}

extern "C" void kernel_launch(void* const* d_in, const int* in_sizes, int n_in,
                              void* d_out, int out_size) {
    const int*   ids     = (const int*)  d_in[0];
    const float* tok_emb = (const float*)d_in[1];
    const float* pos_emb = (const float*)d_in[2];
    const float* in_w    = (const float*)d_in[3];
    const float* in_b    = (const float*)d_in[4];
    const float* ch_w1   = (const float*)d_in[5];
    const float* ch_b1   = (const float*)d_in[6];
    const float* ch_w2   = (const float*)d_in[7];
    const float* ch_b2   = (const float*)d_in[8];
    const float* qe_w1   = (const float*)d_in[9];
    const float* qe_b1   = (const float*)d_in[10];
    const float* qe_w2   = (const float*)d_in[11];
    const float* qe_b2   = (const float*)d_in[12];
    const float* q_w     = (const float*)d_in[13];
    const float* q_b     = (const float*)d_in[14];
    const float* k_w     = (const float*)d_in[15];
    const float* k_b     = (const float*)d_in[16];
    const float* v_w     = (const float*)d_in[17];
    const float* v_b     = (const float*)d_in[18];
    const float* o_w     = (const float*)d_in[19];
    const float* o_b     = (const float*)d_in[20];
    const float* f_w1    = (const float*)d_in[21];
    const float* f_b1    = (const float*)d_in[22];
    const float* f_w2    = (const float*)d_in[23];
    const float* f_b2    = (const float*)d_in[24];
    const float* ln1_g   = (const float*)d_in[25];
    const float* ln1_b   = (const float*)d_in[26];
    const float* ln2_g   = (const float*)d_in[27];
    const float* ln2_b   = (const float*)d_in[28];
    const float* out_w   = (const float*)d_in[29];
    const float* out_b   = (const float*)d_in[30];
    float* logits = (float*)d_out;

    float *h, *x, *q, *k, *v, *ao, *mid, *avg, *cmid, *cenc;
    unsigned* sel;
    cudaGetSymbolAddress((void**)&h,   g_h);
    cudaGetSymbolAddress((void**)&x,   g_x);
    cudaGetSymbolAddress((void**)&q,   g_q);
    cudaGetSymbolAddress((void**)&k,   g_k);
    cudaGetSymbolAddress((void**)&v,   g_v);
    cudaGetSymbolAddress((void**)&ao,  g_ao);
    cudaGetSymbolAddress((void**)&mid, g_mid);
    cudaGetSymbolAddress((void**)&avg, g_avg);
    cudaGetSymbolAddress((void**)&cmid,g_cmid);
    cudaGetSymbolAddress((void**)&cenc,g_cenc);
    cudaGetSymbolAddress((void**)&sel, g_sel);

    // embeddings -> x; input projection -> h
    embed_kernel<<<R_, 256>>>(ids, tok_emb, pos_emb, x);
    launch_gemm(x, in_w, in_b, nullptr, h, R_, E_, H_, 0);

    // chunk encodings
    chunk_avg_kernel<<<dim3(NC_, B_), 256>>>(h, ids, avg);
    launch_gemm(avg,  ch_w1, ch_b1, nullptr, cmid, B_ * NC_, H_,  HH_, 1);
    launch_gemm(cmid, ch_w2, ch_b2, nullptr, cenc, B_ * NC_, HH_, H_,  0);

    for (int i = 0; i < L_; i++) {
        // query encodings + chunk selection
        launch_gemm(h,   qe_w1, qe_b1, nullptr, mid, R_, H_,  HH_, 1);
        launch_gemm(mid, qe_w2, qe_b2, nullptr, x,   R_, HH_, H_,  0);
        topk_kernel<<<dim3(S_, B_), 512>>>(x, cenc, sel);

        // attention block
        ln_kernel<<<R_, 256>>>(h, ln1_g + i * H_, ln1_b + i * H_, x);
        launch_gemm(x, q_w + (size_t)i * H_ * H_, q_b + i * H_, nullptr, q, R_, H_, H_, 0);
        launch_gemm(x, k_w + (size_t)i * H_ * H_, k_b + i * H_, nullptr, k, R_, H_, H_, 0);
        launch_gemm(x, v_w + (size_t)i * H_ * H_, v_b + i * H_, nullptr, v, R_, H_, H_, 0);
        attn_kernel<<<dim3(S_, NH_, B_), 128>>>(q, k, v, sel, ids, ao);
        launch_gemm(ao, o_w + (size_t)i * H_ * H_, o_b + i * H_, h, h, R_, H_, H_, 0);

        // FFN block
        ln_kernel<<<R_, 256>>>(h, ln2_g + i * H_, ln2_b + i * H_, x);
        launch_gemm(x,   f_w1 + (size_t)i * H_ * FF_, f_b1 + i * FF_, nullptr, mid, R_, H_,  FF_, 2);
        launch_gemm(mid, f_w2 + (size_t)i * FF_ * H_, f_b2 + i * H_,  h,       h,   R_, FF_, H_,  0);
    }

    // output logits
    launch_gemm(h, out_w, out_b, nullptr, logits, R_, H_, V_, 0);
}